// round 7
// baseline (speedup 1.0000x reference)
#include <cuda_runtime.h>
#include <math.h>

#define BB 8
#define NN 512
#define FF 64
#define EE 16
#define HH 4
#define HD 16
#define NPOS (BB*NN*NN)    // 2097152
#define ROWS (BB*NN)       // 4096

// ---------------- scratch ------------------------------------------------------
__device__ float g_h  [ROWS*FF];
__device__ float g_sr [ROWS*HH];
__device__ float g_sc [ROWS*HH];
__device__ float g_se [NPOS];
__device__ float g_msg[ROWS*FF];

// ---------------- packed f32x2 helpers ----------------------------------------
union f2u { float2 f; unsigned long long u; };

__device__ __forceinline__ float2 ffma2(float2 a, float2 b, float2 c) {
    f2u A, Bv, C, D; A.f = a; Bv.f = b; C.f = c;
    asm("fma.rn.f32x2 %0, %1, %2, %3;" : "=l"(D.u) : "l"(A.u), "l"(Bv.u), "l"(C.u));
    return D.f;
}
__device__ __forceinline__ float2 fadd2(float2 a, float2 b) {
    f2u A, Bv, D; A.f = a; Bv.f = b;
    asm("add.rn.f32x2 %0, %1, %2;" : "=l"(D.u) : "l"(A.u), "l"(Bv.u));
    return D.f;
}
__device__ __forceinline__ float2 fmul2(float2 a, float2 b) {
    f2u A, Bv, D; A.f = a; Bv.f = b;
    asm("mul.rn.f32x2 %0, %1, %2;" : "=l"(D.u) : "l"(A.u), "l"(Bv.u));
    return D.f;
}
__device__ __forceinline__ float2 celu2(float2 a) {
    return make_float2(fmaxf(a.x, 0.f) + __expf(fminf(a.x, 0.f)) - 1.f,
                       fmaxf(a.y, 0.f) + __expf(fminf(a.y, 0.f)) - 1.f);
}

// ---------------- K1: node LN -> Wn GEMM -> sr/sc (32 rows / block) ------------
__global__ __launch_bounds__(256) void k_node(
        const float* __restrict__ node, const float* __restrict__ g1,
        const float* __restrict__ b1, const float* __restrict__ Wn,
        const float* __restrict__ bn, const float* __restrict__ A) {
    __shared__ __align__(16) float ns[32*68];
    __shared__ float Wns[64*65];
    __shared__ __align__(16) float hs[32*68];
    __shared__ float arow[HD], acol[HD];

    int tid = threadIdx.x;
    int row0 = blockIdx.x * 32;

    if (tid < HD) {
        float s = 0.f;
        #pragma unroll
        for (int h = 0; h < HH; h++) s += A[h*48 + tid];
        arow[tid] = s;
    } else if (tid < 2*HD) {
        int x = tid - HD; float s = 0.f;
        #pragma unroll
        for (int h = 0; h < HH; h++) s += A[h*48 + HD + x];
        acol[x] = s;
    }

    {
        const float4* src = (const float4*)(node + (size_t)row0 * FF);
        #pragma unroll
        for (int i = tid; i < 32*16; i += 256) {
            int r = i >> 4, c4 = i & 15;
            *(float4*)&ns[r*68 + c4*4] = src[i];
        }
    }
    #pragma unroll
    for (int i = tid; i < 64*64; i += 256) {
        int f = i >> 6, k = i & 63;
        Wns[f*65 + k] = Wn[i];
    }
    __syncthreads();

    {
        int r = tid >> 3, sub = tid & 7;
        float s = 0.f;
        #pragma unroll
        for (int t = 0; t < 8; t++) s += ns[r*68 + sub + 8*t];
        s += __shfl_xor_sync(0xffffffffu, s, 1);
        s += __shfl_xor_sync(0xffffffffu, s, 2);
        s += __shfl_xor_sync(0xffffffffu, s, 4);
        float mu = s * (1.f/FF);
        float q = 0.f;
        #pragma unroll
        for (int t = 0; t < 8; t++) { float d = ns[r*68 + sub + 8*t] - mu; q += d*d; }
        q += __shfl_xor_sync(0xffffffffu, q, 1);
        q += __shfl_xor_sync(0xffffffffu, q, 2);
        q += __shfl_xor_sync(0xffffffffu, q, 4);
        float rs = rsqrtf(q * (1.f/FF) + 1e-5f);
        #pragma unroll
        for (int t = 0; t < 8; t++) {
            int k = sub + 8*t;
            ns[r*68 + k] = (ns[r*68 + k] - mu) * rs * g1[k] + b1[k];
        }
    }
    __syncthreads();

    {
        int f  = tid & 63;
        int rg = tid >> 6;
        float acc[8];
        float bv = bn[f];
        #pragma unroll
        for (int t = 0; t < 8; t++) acc[t] = bv;
        #pragma unroll 8
        for (int k = 0; k < 64; k++) {
            float wv = Wns[f*65 + k];
            #pragma unroll
            for (int t = 0; t < 8; t++)
                acc[t] = fmaf(ns[(rg*8 + t)*68 + k], wv, acc[t]);
        }
        #pragma unroll
        for (int t = 0; t < 8; t++) {
            int r = rg*8 + t;
            g_h[(size_t)(row0 + r)*FF + f] = acc[t];
            hs[r*68 + f] = acc[t];
        }
    }
    __syncthreads();

    if (tid < 128) {
        int r = tid >> 2, hh = tid & 3;
        float sr = 0.f, sc = 0.f;
        #pragma unroll
        for (int x = 0; x < HD; x++) {
            float hv = hs[r*68 + hh*HD + x];
            sr = fmaf(hv, arow[x], sr);
            sc = fmaf(hv, acol[x], sc);
        }
        g_sr[(size_t)(row0 + r)*HH + hh] = sr;
        g_sc[(size_t)(row0 + r)*HH + hh] = sc;
    }
}

// ---------------- K2: edge pipeline, 2 positions/thread (low reg pressure) -----
// 128 threads, 256 positions per block. Thread t owns positions t and t+128.
__global__ __launch_bounds__(128) void k_edge(
    const float* __restrict__ edge, const int* __restrict__ adj,
    const float* __restrict__ g2, const float* __restrict__ b2,
    const float* __restrict__ We1, const float* __restrict__ be1,
    const float* __restrict__ We2, const float* __restrict__ be2,
    const float* __restrict__ lg, const float* __restrict__ lb,
    const float* __restrict__ A,
    float* __restrict__ e_out, float* __restrict__ adj_out) {

    // W1t[kk][k]: We1[kk][k]*g2[k], duplicated float2, contiguous in k
    // W2t[kk][o]: We2[o][kk],       duplicated float2, contiguous in o
    __shared__ __align__(16) float2 W1t[32*16], W2t[32*16];
    __shared__ float2 be1f[32], be2s[EE], lneg[EE], lneb[EE], aes[EE];

    int tid = threadIdx.x;
    for (int i = tid; i < 512; i += 128) {
        int k = i & 15;
        float w1 = We1[i] * g2[k];                 // i = kk*16 + k
        W1t[i] = make_float2(w1, w1);
        int kk2 = i >> 4, o2 = i & 15;
        float w2 = We2[o2*32 + kk2];
        W2t[i] = make_float2(w2, w2);
    }
    if (tid < 32) {
        float s = be1[tid];
        #pragma unroll
        for (int k = 0; k < 16; k++) s += b2[k] * We1[tid*16 + k];
        be1f[tid] = make_float2(s, s);
    }
    if (tid < EE) {
        lneg[tid] = make_float2(lg[tid], lg[tid]);
        lneb[tid] = make_float2(lb[tid], lb[tid]);
        be2s[tid] = make_float2(be2[tid], be2[tid]);
        float s = 0.f;
        #pragma unroll
        for (int h = 0; h < HH; h++) s += A[h*48 + 2*HD + tid];
        aes[tid] = make_float2(s, s);
    }

    // adj -> float (coalesced, 256 ints per block)
    size_t base = (size_t)blockIdx.x * 256;
    if (tid < 64) {
        int4 av = ((const int4*)(adj + base))[tid];
        ((float4*)(adj_out + base))[tid] =
            make_float4((float)av.x, (float)av.y, (float)av.z, (float)av.w);
    }
    __syncthreads();

    const float4* e4 = (const float4*)edge;
    const float2 zero2 = make_float2(0.f, 0.f);
    const float2 neg1  = make_float2(-1.f, -1.f);
    const float2 inv16 = make_float2(1.f/16.f, 1.f/16.f);

    size_t pA = base + tid, pB = base + tid + 128;

    float2 X[EE];
    {
        float fa[EE], fb[EE];
        #pragma unroll
        for (int i = 0; i < 4; i++) {
            *(float4*)&fa[i*4] = e4[pA*4 + i];
            *(float4*)&fb[i*4] = e4[pB*4 + i];
        }
        #pragma unroll
        for (int k = 0; k < EE; k++) X[k] = make_float2(fa[k], fb[k]);
    }

    // LN over E -> X = (x - mu) * rs  (gamma/beta folded into W1t/be1f)
    {
        float2 s = zero2;
        #pragma unroll
        for (int k = 0; k < EE; k++) s = fadd2(s, X[k]);
        float2 mu = fmul2(s, inv16);
        float2 q = zero2;
        #pragma unroll
        for (int k = 0; k < EE; k++) { float2 d = ffma2(mu, neg1, X[k]); q = ffma2(d, d, q); }
        float2 v = fmul2(q, inv16);
        float2 rs = make_float2(rsqrtf(v.x + 1e-5f), rsqrtf(v.y + 1e-5f));
        #pragma unroll
        for (int k = 0; k < EE; k++) X[k] = fmul2(ffma2(mu, neg1, X[k]), rs);
    }

    // fused GEMM1 -> celu -> GEMM2; 4 FMA chains in GEMM1; LDS.128 weights
    float2 Y[EE];
    #pragma unroll
    for (int o = 0; o < EE; o++) Y[o] = be2s[o];
    #pragma unroll 4
    for (int kk = 0; kk < 32; kk++) {
        const float4* w1p = (const float4*)&W1t[kk*16];
        float2 a0 = be1f[kk], a1 = zero2, a2 = zero2, a3 = zero2;
        #pragma unroll
        for (int q = 0; q < 4; q++) {
            float4 wva = w1p[2*q];
            float4 wvb = w1p[2*q + 1];
            a0 = ffma2(X[4*q+0], make_float2(wva.x, wva.y), a0);
            a1 = ffma2(X[4*q+1], make_float2(wva.z, wva.w), a1);
            a2 = ffma2(X[4*q+2], make_float2(wvb.x, wvb.y), a2);
            a3 = ffma2(X[4*q+3], make_float2(wvb.z, wvb.w), a3);
        }
        float2 h = celu2(fadd2(fadd2(a0, a1), fadd2(a2, a3)));
        const float4* w2p = (const float4*)&W2t[kk*16];
        #pragma unroll
        for (int q = 0; q < 8; q++) {
            float4 wv = w2p[q];
            Y[2*q]   = ffma2(h, make_float2(wv.x, wv.y), Y[2*q]);
            Y[2*q+1] = ffma2(h, make_float2(wv.z, wv.w), Y[2*q+1]);
        }
    }

    // residual (edge reload: L2-hot)
    {
        float fa[EE], fb[EE];
        #pragma unroll
        for (int i = 0; i < 4; i++) {
            *(float4*)&fa[i*4] = e4[pA*4 + i];
            *(float4*)&fb[i*4] = e4[pB*4 + i];
        }
        #pragma unroll
        for (int k = 0; k < EE; k++)
            Y[k] = fadd2(Y[k], make_float2(fa[k], fb[k]));
    }

    // final LN + se
    {
        float2 s = zero2;
        #pragma unroll
        for (int k = 0; k < EE; k++) s = fadd2(s, Y[k]);
        float2 mu = fmul2(s, inv16);
        float2 q = zero2;
        #pragma unroll
        for (int k = 0; k < EE; k++) { float2 d = ffma2(mu, neg1, Y[k]); q = ffma2(d, d, q); }
        float2 v = fmul2(q, inv16);
        float2 rs = make_float2(rsqrtf(v.x + 1e-5f), rsqrtf(v.y + 1e-5f));
        float2 se = zero2;
        #pragma unroll
        for (int k = 0; k < EE; k++) {
            float2 d = ffma2(mu, neg1, Y[k]);
            Y[k] = ffma2(d, fmul2(rs, lneg[k]), lneb[k]);
            se = ffma2(Y[k], aes[k], se);
        }
        g_se[pA] = se.x;
        g_se[pB] = se.y;
    }

    // stores (float4 per position)
    {
        float4* eo = (float4*)e_out;
        #pragma unroll
        for (int i = 0; i < 4; i++) {
            eo[pA*4 + i] = make_float4(Y[i*4+0].x, Y[i*4+1].x, Y[i*4+2].x, Y[i*4+3].x);
            eo[pB*4 + i] = make_float4(Y[i*4+0].y, Y[i*4+1].y, Y[i*4+2].y, Y[i*4+3].y);
        }
    }
}

// ---------------- K3: two-pass masked leaky softmax + aggregation --------------
__global__ __launch_bounds__(256) void k_attn(const int* __restrict__ adj) {
    __shared__ __align__(16) float hsm[128*64];
    __shared__ float scs[128*4];

    int tid = threadIdx.x;
    int sub = tid & 3;
    int hh  = (tid >> 2) & 3;
    int il  = tid >> 4;
    int b = blockIdx.y;
    int ig = blockIdx.x * 16 + il;
    int rowi = b*NN + ig;

    const float* sep = g_se + (size_t)rowi * NN;
    const int*   ap  = adj  + (size_t)rowi * NN;
    float sr_v = g_sr[rowi*HH + hh];
    const float* scg = g_sc + (size_t)b*NN*HH;

    float m = -3.4e38f;
    #pragma unroll 4
    for (int t = 0; t < 128; t++) {
        int j = sub + 4*t;
        float lgt = sr_v + scg[j*HH + hh] + sep[j];
        if (ap[j] == 0) lgt = -1e9f;
        lgt = lgt > 0.f ? lgt : 0.2f*lgt;
        lgt = fminf(fmaxf(lgt, -1e9f), 1e9f);
        m = fmaxf(m, lgt);
    }
    m = fmaxf(m, __shfl_xor_sync(0xffffffffu, m, 1));
    m = fmaxf(m, __shfl_xor_sync(0xffffffffu, m, 2));

    float ssum = 0.f;
    float a0 = 0.f, a1 = 0.f, a2 = 0.f, a3 = 0.f;
    for (int jt = 0; jt < 4; jt++) {
        int j0 = jt * 128;
        __syncthreads();
        {
            const float4* hsrc = (const float4*)(g_h + (size_t)(b*NN + j0) * FF);
            #pragma unroll
            for (int i = tid; i < 128*16; i += 256) ((float4*)hsm)[i] = hsrc[i];
            if (tid < 128)
                ((float4*)scs)[tid] = ((const float4*)(scg + (size_t)j0*HH))[tid];
        }
        __syncthreads();
        #pragma unroll 2
        for (int jl = 0; jl < 128; jl++) {
            int j = j0 + jl;
            float lgt = sr_v + scs[jl*4 + hh] + sep[j];
            if (ap[j] == 0) lgt = -1e9f;
            lgt = lgt > 0.f ? lgt : 0.2f*lgt;
            lgt = fminf(fmaxf(lgt, -1e9f), 1e9f);
            float w = __expf(lgt - m);
            ssum += w;
            float4 hv = *(const float4*)(hsm + jl*64 + hh*16 + sub*4);
            a0 = fmaf(w, hv.x, a0);
            a1 = fmaf(w, hv.y, a1);
            a2 = fmaf(w, hv.z, a2);
            a3 = fmaf(w, hv.w, a3);
        }
    }
    float inv = 1.f / ssum;
    *(float4*)(g_msg + (size_t)rowi*FF + hh*16 + sub*4) =
        make_float4(a0*inv, a1*inv, a2*inv, a3*inv);
}

// ---------------- K4: out proj + residual + leaky + LN (32 rows / block) -------
__global__ __launch_bounds__(256) void k_out(
        const float* __restrict__ node, const float* __restrict__ Wo,
        const float* __restrict__ bo, const float* __restrict__ lg,
        const float* __restrict__ lb, float* __restrict__ outp) {
    __shared__ __align__(16) float ms[32*68];
    __shared__ float Wos[64*65];
    __shared__ __align__(16) float hsr[32*68];

    int tid = threadIdx.x;
    int row0 = blockIdx.x * 32;

    {
        const float4* src = (const float4*)(g_msg + (size_t)row0 * FF);
        #pragma unroll
        for (int i = tid; i < 32*16; i += 256) {
            int r = i >> 4, c4 = i & 15;
            *(float4*)&ms[r*68 + c4*4] = src[i];
        }
    }
    #pragma unroll
    for (int i = tid; i < 64*64; i += 256) {
        int f = i >> 6, k = i & 63;
        Wos[f*65 + k] = Wo[i];
    }
    __syncthreads();

    {
        int f  = tid & 63;
        int rg = tid >> 6;
        float acc[8];
        float bv = bo[f];
        #pragma unroll
        for (int t = 0; t < 8; t++) acc[t] = bv;
        #pragma unroll 8
        for (int k = 0; k < 64; k++) {
            float wv = Wos[f*65 + k];
            #pragma unroll
            for (int t = 0; t < 8; t++)
                acc[t] = fmaf(ms[(rg*8 + t)*68 + k], wv, acc[t]);
        }
        #pragma unroll
        for (int t = 0; t < 8; t++) {
            int r = rg*8 + t;
            float v = acc[t] + node[(size_t)(row0 + r)*FF + f];
            v = v > 0.f ? v : 0.2f*v;
            hsr[r*68 + f] = v;
        }
    }
    __syncthreads();

    {
        int r = tid >> 3, sub = tid & 7;
        float s = 0.f;
        #pragma unroll
        for (int t = 0; t < 8; t++) s += hsr[r*68 + sub + 8*t];
        s += __shfl_xor_sync(0xffffffffu, s, 1);
        s += __shfl_xor_sync(0xffffffffu, s, 2);
        s += __shfl_xor_sync(0xffffffffu, s, 4);
        float mu = s * (1.f/FF);
        float q = 0.f;
        #pragma unroll
        for (int t = 0; t < 8; t++) { float d = hsr[r*68 + sub + 8*t] - mu; q += d*d; }
        q += __shfl_xor_sync(0xffffffffu, q, 1);
        q += __shfl_xor_sync(0xffffffffu, q, 2);
        q += __shfl_xor_sync(0xffffffffu, q, 4);
        float rsv = rsqrtf(q * (1.f/FF) + 1e-5f);
        #pragma unroll
        for (int t = 0; t < 8; t++) {
            int k = sub + 8*t;
            outp[(size_t)(row0 + r)*FF + k] = (hsr[r*68 + k] - mu) * rsv * lg[k] + lb[k];
        }
    }
}

// ---------------- launch -------------------------------------------------------
extern "C" void kernel_launch(void* const* d_in, const int* in_sizes, int n_in,
                              void* d_out, int out_size) {
    const float* node  = (const float*)d_in[0];
    const float* edge  = (const float*)d_in[1];
    const int*   adj   = (const int*)  d_in[2];
    const float* ln1_g = (const float*)d_in[3];
    const float* ln1_b = (const float*)d_in[4];
    const float* Wn    = (const float*)d_in[5];
    const float* bn    = (const float*)d_in[6];
    const float* ln2_g = (const float*)d_in[7];
    const float* ln2_b = (const float*)d_in[8];
    const float* We1   = (const float*)d_in[9];
    const float* be1   = (const float*)d_in[10];
    const float* We2   = (const float*)d_in[11];
    const float* be2   = (const float*)d_in[12];
    const float* lne_g = (const float*)d_in[13];
    const float* lne_b = (const float*)d_in[14];
    const float* attnA = (const float*)d_in[15];
    const float* Wo    = (const float*)d_in[16];
    const float* bo    = (const float*)d_in[17];
    const float* lno_g = (const float*)d_in[18];
    const float* lno_b = (const float*)d_in[19];

    float* out     = (float*)d_out;
    float* e_out   = out + (size_t)ROWS * FF;
    float* adj_out = e_out + (size_t)NPOS * EE;

    k_node<<<ROWS/32, 256>>>(node, ln1_g, ln1_b, Wn, bn, attnA);
    k_edge<<<NPOS/256, 128>>>(edge, adj, ln2_g, ln2_b, We1, be1, We2, be2,
                              lne_g, lne_b, attnA, e_out, adj_out);
    k_attn<<<dim3(NN/16, BB), 256>>>(adj);
    k_out<<<ROWS/32, 256>>>(node, Wo, bo, lno_g, lno_b, out);
}

// round 8
// speedup vs baseline: 1.2218x; 1.2218x over previous
#include <cuda_runtime.h>
#include <math.h>
#include <stdint.h>

#define BB 8
#define NN 512
#define FF 64
#define EE 16
#define HH 4
#define HD 16
#define NPOS (BB*NN*NN)    // 2097152
#define ROWS (BB*NN)       // 4096

// ---------------- scratch ------------------------------------------------------
__device__ float g_h  [ROWS*FF];
__device__ float g_sr [ROWS*HH];
__device__ float g_sc [ROWS*HH];
__device__ float g_se [NPOS];
__device__ float g_msg[ROWS*FF];

__device__ __forceinline__ float celu1(float x) {
    return fmaxf(x, 0.f) + __expf(fminf(x, 0.f)) - 1.f;
}
__device__ __forceinline__ uint32_t f2tf32(float x) {
    uint32_t r;
    asm("cvt.rna.tf32.f32 %0, %1;" : "=r"(r) : "f"(x));
    return r;
}
__device__ __forceinline__ void mma_tf32(float* d, uint32_t a0, uint32_t a1,
                                         uint32_t a2, uint32_t a3,
                                         uint32_t b0, uint32_t b1) {
    asm volatile(
        "mma.sync.aligned.m16n8k8.row.col.f32.tf32.tf32.f32 "
        "{%0,%1,%2,%3}, {%4,%5,%6,%7}, {%8,%9}, {%0,%1,%2,%3};\n"
        : "+f"(d[0]), "+f"(d[1]), "+f"(d[2]), "+f"(d[3])
        : "r"(a0), "r"(a1), "r"(a2), "r"(a3), "r"(b0), "r"(b1));
}

// ---------------- K1: node LN -> Wn GEMM -> sr/sc (32 rows / block) ------------
__global__ __launch_bounds__(256) void k_node(
        const float* __restrict__ node, const float* __restrict__ g1,
        const float* __restrict__ b1, const float* __restrict__ Wn,
        const float* __restrict__ bn, const float* __restrict__ A) {
    __shared__ __align__(16) float ns[32*68];
    __shared__ float Wns[64*65];
    __shared__ __align__(16) float hs[32*68];
    __shared__ float arow[HD], acol[HD];

    int tid = threadIdx.x;
    int row0 = blockIdx.x * 32;

    if (tid < HD) {
        float s = 0.f;
        #pragma unroll
        for (int h = 0; h < HH; h++) s += A[h*48 + tid];
        arow[tid] = s;
    } else if (tid < 2*HD) {
        int x = tid - HD; float s = 0.f;
        #pragma unroll
        for (int h = 0; h < HH; h++) s += A[h*48 + HD + x];
        acol[x] = s;
    }

    {
        const float4* src = (const float4*)(node + (size_t)row0 * FF);
        #pragma unroll
        for (int i = tid; i < 32*16; i += 256) {
            int r = i >> 4, c4 = i & 15;
            *(float4*)&ns[r*68 + c4*4] = src[i];
        }
    }
    #pragma unroll
    for (int i = tid; i < 64*64; i += 256) {
        int f = i >> 6, k = i & 63;
        Wns[f*65 + k] = Wn[i];
    }
    __syncthreads();

    {
        int r = tid >> 3, sub = tid & 7;
        float s = 0.f;
        #pragma unroll
        for (int t = 0; t < 8; t++) s += ns[r*68 + sub + 8*t];
        s += __shfl_xor_sync(0xffffffffu, s, 1);
        s += __shfl_xor_sync(0xffffffffu, s, 2);
        s += __shfl_xor_sync(0xffffffffu, s, 4);
        float mu = s * (1.f/FF);
        float q = 0.f;
        #pragma unroll
        for (int t = 0; t < 8; t++) { float d = ns[r*68 + sub + 8*t] - mu; q += d*d; }
        q += __shfl_xor_sync(0xffffffffu, q, 1);
        q += __shfl_xor_sync(0xffffffffu, q, 2);
        q += __shfl_xor_sync(0xffffffffu, q, 4);
        float rs = rsqrtf(q * (1.f/FF) + 1e-5f);
        #pragma unroll
        for (int t = 0; t < 8; t++) {
            int k = sub + 8*t;
            ns[r*68 + k] = (ns[r*68 + k] - mu) * rs * g1[k] + b1[k];
        }
    }
    __syncthreads();

    {
        int f  = tid & 63;
        int rg = tid >> 6;
        float acc[8];
        float bv = bn[f];
        #pragma unroll
        for (int t = 0; t < 8; t++) acc[t] = bv;
        #pragma unroll 8
        for (int k = 0; k < 64; k++) {
            float wv = Wns[f*65 + k];
            #pragma unroll
            for (int t = 0; t < 8; t++)
                acc[t] = fmaf(ns[(rg*8 + t)*68 + k], wv, acc[t]);
        }
        #pragma unroll
        for (int t = 0; t < 8; t++) {
            int r = rg*8 + t;
            g_h[(size_t)(row0 + r)*FF + f] = acc[t];
            hs[r*68 + f] = acc[t];
        }
    }
    __syncthreads();

    if (tid < 128) {
        int r = tid >> 2, hh = tid & 3;
        float sr = 0.f, sc = 0.f;
        #pragma unroll
        for (int x = 0; x < HD; x++) {
            float hv = hs[r*68 + hh*HD + x];
            sr = fmaf(hv, arow[x], sr);
            sc = fmaf(hv, acol[x], sc);
        }
        g_sr[(size_t)(row0 + r)*HH + hh] = sr;
        g_sc[(size_t)(row0 + r)*HH + hh] = sc;
    }
}

// ---------------- K2: edge pipeline with tf32 mma.sync -------------------------
// 128 threads (4 warps), 256 positions/block. Warp w owns positions [w*64, w*64+64).
__global__ __launch_bounds__(128) void k_edge(
    const float* __restrict__ edge, const int* __restrict__ adj,
    const float* __restrict__ g2, const float* __restrict__ b2,
    const float* __restrict__ We1, const float* __restrict__ be1,
    const float* __restrict__ We2, const float* __restrict__ be2,
    const float* __restrict__ lg, const float* __restrict__ lb,
    const float* __restrict__ A,
    float* __restrict__ e_out, float* __restrict__ adj_out) {

    __shared__ __align__(16) float Xs[256*20];   // original edge rows (fp32)
    __shared__ __align__(16) float An[256*20];   // tf32 LN'd X, then Ys (fp32)
    __shared__ __align__(16) float Hs[4*16*36];  // per-warp hidden tiles (tf32 bits)
    __shared__ float be1f[32], be2s[EE], lgs[EE], lbs[EE], aesm[EE];

    int tid  = threadIdx.x;
    int lane = tid & 31, w = tid >> 5;
    int gid  = lane >> 2, tig = lane & 3;
    size_t base = (size_t)blockIdx.x * 256;

    if (tid < EE) {
        be2s[tid] = be2[tid];
        lgs[tid]  = lg[tid];
        lbs[tid]  = lb[tid];
        float s = 0.f;
        #pragma unroll
        for (int h = 0; h < HH; h++) s += A[h*48 + 2*HD + tid];
        aesm[tid] = s;
    }
    if (tid < 32) {
        float s = be1[tid];
        #pragma unroll
        for (int k = 0; k < 16; k++) s += b2[k] * We1[tid*16 + k];
        be1f[tid] = s;
    }
    // adj -> float (256 ints)
    if (tid < 64) {
        int4 av = ((const int4*)(adj + base))[tid];
        ((float4*)(adj_out + base))[tid] =
            make_float4((float)av.x, (float)av.y, (float)av.z, (float)av.w);
    }
    // stage edge tile (coalesced)
    {
        const float4* src = (const float4*)edge + base*4;
        #pragma unroll
        for (int i = tid; i < 1024; i += 128)
            *(float4*)&Xs[(i>>2)*20 + (i&3)*4] = src[i];
    }

    // weight B-fragments in registers (ln2 gamma folded into W1)
    uint32_t w1b[4][2][2];    // [nt][kt][b0/b1]
    #pragma unroll
    for (int nt = 0; nt < 4; nt++)
        #pragma unroll
        for (int kt = 0; kt < 2; kt++) {
            int n = nt*8 + gid, k = kt*8 + tig;
            w1b[nt][kt][0] = f2tf32(We1[n*16 + k]     * g2[k]);
            w1b[nt][kt][1] = f2tf32(We1[n*16 + k + 4] * g2[k + 4]);
        }
    uint32_t w2b[2][4][2];    // [nt2][kt][b0/b1]
    #pragma unroll
    for (int nt2 = 0; nt2 < 2; nt2++)
        #pragma unroll
        for (int kt = 0; kt < 4; kt++) {
            int n = nt2*8 + gid, k = kt*8 + tig;
            w2b[nt2][kt][0] = f2tf32(We2[n*32 + k]);
            w2b[nt2][kt][1] = f2tf32(We2[n*32 + k + 4]);
        }
    __syncthreads();

    // LN per position (fp32) -> An holds tf32 bits of (x-mu)*rs
    #pragma unroll
    for (int pp = 0; pp < 2; pp++) {
        int p = tid + pp*128;
        float x[16];
        #pragma unroll
        for (int c = 0; c < 4; c++) *(float4*)&x[c*4] = *(float4*)&Xs[p*20 + c*4];
        float s = 0.f;
        #pragma unroll
        for (int k = 0; k < 16; k++) s += x[k];
        float mu = s * (1.f/16.f);
        float q = 0.f;
        #pragma unroll
        for (int k = 0; k < 16; k++) { float d = x[k] - mu; q += d*d; }
        float rs = rsqrtf(q * (1.f/16.f) + 1e-5f);
        #pragma unroll
        for (int c = 0; c < 4; c++) {
            float4 v;
            v.x = __uint_as_float(f2tf32((x[c*4+0] - mu) * rs));
            v.y = __uint_as_float(f2tf32((x[c*4+1] - mu) * rs));
            v.z = __uint_as_float(f2tf32((x[c*4+2] - mu) * rs));
            v.w = __uint_as_float(f2tf32((x[c*4+3] - mu) * rs));
            *(float4*)&An[p*20 + c*4] = v;
        }
    }
    __syncthreads();

    // per-warp MMA pipeline over 4 pos-tiles of 16
    float* HsW = &Hs[w*16*36];
    int rb0 = w*64;
    #pragma unroll
    for (int pt = 0; pt < 4; pt++) {
        int rb = rb0 + pt*16;
        // GEMM1: [16 pos x 16 chan] @ [16 x 32] -> D[4 nt][4]
        float d[4][4];
        #pragma unroll
        for (int nt = 0; nt < 4; nt++)
            #pragma unroll
            for (int j = 0; j < 4; j++) d[nt][j] = 0.f;
        #pragma unroll
        for (int kt = 0; kt < 2; kt++) {
            uint32_t a0 = __float_as_uint(An[(rb+gid  )*20 + kt*8 + tig]);
            uint32_t a1 = __float_as_uint(An[(rb+gid+8)*20 + kt*8 + tig]);
            uint32_t a2 = __float_as_uint(An[(rb+gid  )*20 + kt*8 + tig + 4]);
            uint32_t a3 = __float_as_uint(An[(rb+gid+8)*20 + kt*8 + tig + 4]);
            #pragma unroll
            for (int nt = 0; nt < 4; nt++)
                mma_tf32(d[nt], a0, a1, a2, a3, w1b[nt][kt][0], w1b[nt][kt][1]);
        }
        // bias + celu + cvt -> Hs (tf32 bits)
        #pragma unroll
        for (int nt = 0; nt < 4; nt++) {
            int c0 = nt*8 + 2*tig;
            float b0v = be1f[c0], b1v = be1f[c0+1];
            float h0 = celu1(d[nt][0] + b0v), h1 = celu1(d[nt][1] + b1v);
            float h2 = celu1(d[nt][2] + b0v), h3 = celu1(d[nt][3] + b1v);
            *(float2*)&HsW[gid*36 + c0] =
                make_float2(__uint_as_float(f2tf32(h0)), __uint_as_float(f2tf32(h1)));
            *(float2*)&HsW[(gid+8)*36 + c0] =
                make_float2(__uint_as_float(f2tf32(h2)), __uint_as_float(f2tf32(h3)));
        }
        __syncwarp();
        // GEMM2: [16 pos x 32 hid] @ [32 x 16] -> D2[2 nt2][4]
        float d2[2][4];
        #pragma unroll
        for (int nt2 = 0; nt2 < 2; nt2++)
            #pragma unroll
            for (int j = 0; j < 4; j++) d2[nt2][j] = 0.f;
        #pragma unroll
        for (int kt = 0; kt < 4; kt++) {
            uint32_t a0 = __float_as_uint(HsW[gid*36     + kt*8 + tig]);
            uint32_t a1 = __float_as_uint(HsW[(gid+8)*36 + kt*8 + tig]);
            uint32_t a2 = __float_as_uint(HsW[gid*36     + kt*8 + tig + 4]);
            uint32_t a3 = __float_as_uint(HsW[(gid+8)*36 + kt*8 + tig + 4]);
            mma_tf32(d2[0], a0, a1, a2, a3, w2b[0][kt][0], w2b[0][kt][1]);
            mma_tf32(d2[1], a0, a1, a2, a3, w2b[1][kt][0], w2b[1][kt][1]);
        }
        __syncwarp();
        // store raw MLP output (fp32) into An slice (Ys)
        #pragma unroll
        for (int nt2 = 0; nt2 < 2; nt2++) {
            int c0 = nt2*8 + 2*tig;
            *(float2*)&An[(rb+gid  )*20 + c0] = make_float2(d2[nt2][0], d2[nt2][1]);
            *(float2*)&An[(rb+gid+8)*20 + c0] = make_float2(d2[nt2][2], d2[nt2][3]);
        }
        __syncwarp();
    }

    // residual + final LN + se (fp32 exact), per thread 2 positions of own warp slice
    #pragma unroll
    for (int pp = 0; pp < 2; pp++) {
        int p = w*64 + lane + pp*32;
        float y[16];
        float s = 0.f;
        #pragma unroll
        for (int k = 0; k < 16; k++) {
            y[k] = An[p*20 + k] + be2s[k] + Xs[p*20 + k];
            s += y[k];
        }
        float mu = s * (1.f/16.f);
        float q = 0.f;
        #pragma unroll
        for (int k = 0; k < 16; k++) { float d = y[k] - mu; q += d*d; }
        float rs = rsqrtf(q * (1.f/16.f) + 1e-5f);
        float se = 0.f;
        #pragma unroll
        for (int k = 0; k < 16; k++) {
            float yv = (y[k] - mu) * rs * lgs[k] + lbs[k];
            An[p*20 + k] = yv;
            se = fmaf(yv, aesm[k], se);
        }
        g_se[base + p] = se;
    }
    __syncthreads();

    // coalesced store of e
    {
        float4* eo = (float4*)e_out + base*4;
        #pragma unroll
        for (int i = tid; i < 1024; i += 128)
            eo[i] = *(float4*)&An[(i>>2)*20 + (i&3)*4];
    }
}

// ---------------- K3: two-pass masked leaky softmax + aggregation --------------
__global__ __launch_bounds__(256) void k_attn(const int* __restrict__ adj) {
    __shared__ __align__(16) float hsm[128*64];
    __shared__ float scs[128*4];

    int tid = threadIdx.x;
    int sub = tid & 3;
    int hh  = (tid >> 2) & 3;
    int il  = tid >> 4;
    int b = blockIdx.y;
    int ig = blockIdx.x * 16 + il;
    int rowi = b*NN + ig;

    const float* sep = g_se + (size_t)rowi * NN;
    const int*   ap  = adj  + (size_t)rowi * NN;
    float sr_v = g_sr[rowi*HH + hh];
    const float* scg = g_sc + (size_t)b*NN*HH;

    float m = -3.4e38f;
    #pragma unroll 4
    for (int t = 0; t < 128; t++) {
        int j = sub + 4*t;
        float lgt = sr_v + scg[j*HH + hh] + sep[j];
        if (ap[j] == 0) lgt = -1e9f;
        lgt = lgt > 0.f ? lgt : 0.2f*lgt;
        lgt = fminf(fmaxf(lgt, -1e9f), 1e9f);
        m = fmaxf(m, lgt);
    }
    m = fmaxf(m, __shfl_xor_sync(0xffffffffu, m, 1));
    m = fmaxf(m, __shfl_xor_sync(0xffffffffu, m, 2));

    float ssum = 0.f;
    float a0 = 0.f, a1 = 0.f, a2 = 0.f, a3 = 0.f;
    for (int jt = 0; jt < 4; jt++) {
        int j0 = jt * 128;
        __syncthreads();
        {
            const float4* hsrc = (const float4*)(g_h + (size_t)(b*NN + j0) * FF);
            #pragma unroll
            for (int i = tid; i < 128*16; i += 256) ((float4*)hsm)[i] = hsrc[i];
            if (tid < 128)
                ((float4*)scs)[tid] = ((const float4*)(scg + (size_t)j0*HH))[tid];
        }
        __syncthreads();
        #pragma unroll 2
        for (int jl = 0; jl < 128; jl++) {
            int j = j0 + jl;
            float lgt = sr_v + scs[jl*4 + hh] + sep[j];
            if (ap[j] == 0) lgt = -1e9f;
            lgt = lgt > 0.f ? lgt : 0.2f*lgt;
            lgt = fminf(fmaxf(lgt, -1e9f), 1e9f);
            float w = __expf(lgt - m);
            ssum += w;
            float4 hv = *(const float4*)(hsm + jl*64 + hh*16 + sub*4);
            a0 = fmaf(w, hv.x, a0);
            a1 = fmaf(w, hv.y, a1);
            a2 = fmaf(w, hv.z, a2);
            a3 = fmaf(w, hv.w, a3);
        }
    }
    float inv = 1.f / ssum;
    *(float4*)(g_msg + (size_t)rowi*FF + hh*16 + sub*4) =
        make_float4(a0*inv, a1*inv, a2*inv, a3*inv);
}

// ---------------- K4: out proj + residual + leaky + LN (32 rows / block) -------
__global__ __launch_bounds__(256) void k_out(
        const float* __restrict__ node, const float* __restrict__ Wo,
        const float* __restrict__ bo, const float* __restrict__ lg,
        const float* __restrict__ lb, float* __restrict__ outp) {
    __shared__ __align__(16) float ms[32*68];
    __shared__ float Wos[64*65];
    __shared__ __align__(16) float hsr[32*68];

    int tid = threadIdx.x;
    int row0 = blockIdx.x * 32;

    {
        const float4* src = (const float4*)(g_msg + (size_t)row0 * FF);
        #pragma unroll
        for (int i = tid; i < 32*16; i += 256) {
            int r = i >> 4, c4 = i & 15;
            *(float4*)&ms[r*68 + c4*4] = src[i];
        }
    }
    #pragma unroll
    for (int i = tid; i < 64*64; i += 256) {
        int f = i >> 6, k = i & 63;
        Wos[f*65 + k] = Wo[i];
    }
    __syncthreads();

    {
        int f  = tid & 63;
        int rg = tid >> 6;
        float acc[8];
        float bv = bo[f];
        #pragma unroll
        for (int t = 0; t < 8; t++) acc[t] = bv;
        #pragma unroll 8
        for (int k = 0; k < 64; k++) {
            float wv = Wos[f*65 + k];
            #pragma unroll
            for (int t = 0; t < 8; t++)
                acc[t] = fmaf(ms[(rg*8 + t)*68 + k], wv, acc[t]);
        }
        #pragma unroll
        for (int t = 0; t < 8; t++) {
            int r = rg*8 + t;
            float v = acc[t] + node[(size_t)(row0 + r)*FF + f];
            v = v > 0.f ? v : 0.2f*v;
            hsr[r*68 + f] = v;
        }
    }
    __syncthreads();

    {
        int r = tid >> 3, sub = tid & 7;
        float s = 0.f;
        #pragma unroll
        for (int t = 0; t < 8; t++) s += hsr[r*68 + sub + 8*t];
        s += __shfl_xor_sync(0xffffffffu, s, 1);
        s += __shfl_xor_sync(0xffffffffu, s, 2);
        s += __shfl_xor_sync(0xffffffffu, s, 4);
        float mu = s * (1.f/FF);
        float q = 0.f;
        #pragma unroll
        for (int t = 0; t < 8; t++) { float d = hsr[r*68 + sub + 8*t] - mu; q += d*d; }
        q += __shfl_xor_sync(0xffffffffu, q, 1);
        q += __shfl_xor_sync(0xffffffffu, q, 2);
        q += __shfl_xor_sync(0xffffffffu, q, 4);
        float rsv = rsqrtf(q * (1.f/FF) + 1e-5f);
        #pragma unroll
        for (int t = 0; t < 8; t++) {
            int k = sub + 8*t;
            outp[(size_t)(row0 + r)*FF + k] = (hsr[r*68 + k] - mu) * rsv * lg[k] + lb[k];
        }
    }
}

// ---------------- launch -------------------------------------------------------
extern "C" void kernel_launch(void* const* d_in, const int* in_sizes, int n_in,
                              void* d_out, int out_size) {
    const float* node  = (const float*)d_in[0];
    const float* edge  = (const float*)d_in[1];
    const int*   adj   = (const int*)  d_in[2];
    const float* ln1_g = (const float*)d_in[3];
    const float* ln1_b = (const float*)d_in[4];
    const float* Wn    = (const float*)d_in[5];
    const float* bn    = (const float*)d_in[6];
    const float* ln2_g = (const float*)d_in[7];
    const float* ln2_b = (const float*)d_in[8];
    const float* We1   = (const float*)d_in[9];
    const float* be1   = (const float*)d_in[10];
    const float* We2   = (const float*)d_in[11];
    const float* be2   = (const float*)d_in[12];
    const float* lne_g = (const float*)d_in[13];
    const float* lne_b = (const float*)d_in[14];
    const float* attnA = (const float*)d_in[15];
    const float* Wo    = (const float*)d_in[16];
    const float* bo    = (const float*)d_in[17];
    const float* lno_g = (const float*)d_in[18];
    const float* lno_b = (const float*)d_in[19];

    float* out     = (float*)d_out;
    float* e_out   = out + (size_t)ROWS * FF;
    float* adj_out = e_out + (size_t)NPOS * EE;

    k_node<<<ROWS/32, 256>>>(node, ln1_g, ln1_b, Wn, bn, attnA);
    k_edge<<<NPOS/256, 128>>>(edge, adj, ln2_g, ln2_b, We1, be1, We2, be2,
                              lne_g, lne_b, attnA, e_out, adj_out);
    k_attn<<<dim3(NN/16, BB), 256>>>(adj);
    k_out<<<ROWS/32, 256>>>(node, Wo, bo, lno_g, lno_b, out);
}